// round 3
// baseline (speedup 1.0000x reference)
#include <cuda_runtime.h>
#include <cuda_bf16.h>
#include <cstdint>

#define BATCH 8
#define NN    2048
#define DD    128
#define BK    64
#define LDT   72   // 64 + 8 pad halves; 144 B row stride: 16B-aligned, 4-bank shift/row
#define NPAIR 136  // 16*17/2 triangular tile pairs

// Scratch (no allocation allowed in kernel_launch)
__device__ __nv_bfloat16 g_Hbf[BATCH * NN * DD];
__device__ float         g_hsq[BATCH * NN];
__device__ float         g_partials[BATCH * NPAIR];

// ---------------------------------------------------------------------------
// Prep: 2 rows per warp (ILP on the shfl chains), float4 loads, no block sync.
// grid 1024 x 256 threads (8 warps x 2 rows = 16 rows per block)
// ---------------------------------------------------------------------------
__global__ __launch_bounds__(256) void prep_kernel(const float* __restrict__ emb) {
    const int w    = threadIdx.x >> 5;
    const int lane = threadIdx.x & 31;
    const int row0 = blockIdx.x * 16 + w * 2;

    float4 v0 = ((const float4*)(emb + (size_t)row0 * DD))[lane];
    float4 v1 = ((const float4*)(emb + (size_t)(row0 + 1) * DD))[lane];

    __nv_bfloat162 a0 = __float22bfloat162_rn(make_float2(v0.x, v0.y));
    __nv_bfloat162 a1 = __float22bfloat162_rn(make_float2(v0.z, v0.w));
    __nv_bfloat162 b0 = __float22bfloat162_rn(make_float2(v1.x, v1.y));
    __nv_bfloat162 b1 = __float22bfloat162_rn(make_float2(v1.z, v1.w));
    uint2 s0, s1;
    s0.x = *(unsigned*)&a0; s0.y = *(unsigned*)&a1;
    s1.x = *(unsigned*)&b0; s1.y = *(unsigned*)&b1;
    ((uint2*)(g_Hbf + (size_t)row0 * DD))[lane]       = s0;
    ((uint2*)(g_Hbf + (size_t)(row0 + 1) * DD))[lane] = s1;

    float sq0 = v0.x * v0.x + v0.y * v0.y + v0.z * v0.z + v0.w * v0.w;
    float sq1 = v1.x * v1.x + v1.y * v1.y + v1.z * v1.z + v1.w * v1.w;
    #pragma unroll
    for (int o = 16; o > 0; o >>= 1) {
        sq0 += __shfl_down_sync(0xffffffffu, sq0, o);
        sq1 += __shfl_down_sync(0xffffffffu, sq1, o);
    }
    if (lane == 0) {
        g_hsq[row0]     = sq0;
        g_hsq[row0 + 1] = sq1;
    }
}

// ---------------------------------------------------------------------------
// m16n8k16 bf16 MMA, fp32 accumulate
// ---------------------------------------------------------------------------
__device__ __forceinline__ void mma16816(float* c, const unsigned* a, const unsigned* b) {
    asm volatile(
        "mma.sync.aligned.m16n8k16.row.col.f32.bf16.bf16.f32 "
        "{%0,%1,%2,%3}, {%4,%5,%6,%7}, {%8,%9}, {%0,%1,%2,%3};\n"
        : "+f"(c[0]), "+f"(c[1]), "+f"(c[2]), "+f"(c[3])
        : "r"(a[0]), "r"(a[1]), "r"(a[2]), "r"(a[3]), "r"(b[0]), "r"(b[1]));
}

// ---------------------------------------------------------------------------
// Main: symmetric-pair tiles + L2 prefetch of the adj footprint so DRAM
// streaming overlaps the MMA phase.
// grid (NPAIR, BATCH), 256 threads (8 warps, 2x4 warp grid over 128x128 tile)
// ---------------------------------------------------------------------------
__global__ __launch_bounds__(256, 2) void main_kernel(const float* __restrict__ adj) {
    __shared__ __align__(16) __nv_bfloat16 sHn[128 * LDT];
    __shared__ __align__(16) __nv_bfloat16 sHm[128 * LDT];
    __shared__ float s_hsqn[128], s_hsqm[128];
    __shared__ float s_red[8];

    // triangular decode: p = tj*(tj+1)/2 + ti, ti <= tj
    const int p = blockIdx.x;
    int tj = (int)((sqrtf(8.f * (float)p + 1.f) - 1.f) * 0.5f);
    while ((tj + 1) * (tj + 2) / 2 <= p) ++tj;
    while (tj * (tj + 1) / 2 > p) --tj;
    const int ti = p - tj * (tj + 1) / 2;

    const int b   = blockIdx.y;
    const int bn0 = ti * 128;   // row tile (n index)
    const int bm0 = tj * 128;   // col tile (m index)
    const bool offd = (ti != tj);

    const int tid  = threadIdx.x;
    const int lane = tid & 31;
    const int w    = tid >> 5;
    const int wr   = (w >> 2) * 64;  // warp row origin within tile
    const int wc   = (w & 3) * 32;   // warp col origin within tile

    // ---- L2 prefetch of the adj tiles this block will stream in the epilogue.
    // A tile: 128 rows x 512 B = 512 cache lines; T tile likewise when off-diag.
    {
        const float* pfA = adj + ((size_t)b * NN + bn0) * NN + bm0;
        const float* pfT = adj + ((size_t)b * NN + bm0) * NN + bn0;
        #pragma unroll
        for (int k = 0; k < 2; ++k) {
            int idx = tid + k * 256;             // 0..511
            int r = idx >> 2, c = (idx & 3) * 32;
            asm volatile("prefetch.global.L2 [%0];" :: "l"(pfA + (size_t)r * NN + c));
            if (offd)
                asm volatile("prefetch.global.L2 [%0];" :: "l"(pfT + (size_t)r * NN + c));
        }
    }

    if (tid < 128) s_hsqn[tid]       = g_hsq[b * NN + bn0 + tid];
    else           s_hsqm[tid - 128] = g_hsq[b * NN + bm0 + (tid - 128)];

    float acc[4][4][4];
    #pragma unroll
    for (int i = 0; i < 4; ++i)
        #pragma unroll
        for (int j = 0; j < 4; ++j)
            #pragma unroll
            for (int k = 0; k < 4; ++k) acc[i][j][k] = 0.f;

    const __nv_bfloat16* Hn = g_Hbf + ((size_t)(b * NN + bn0)) * DD;
    const __nv_bfloat16* Hm = g_Hbf + ((size_t)(b * NN + bm0)) * DD;

    #pragma unroll
    for (int kc = 0; kc < 2; ++kc) {
        __syncthreads();
        const uint4* srcn = (const uint4*)(Hn + kc * BK);
        const uint4* srcm = (const uint4*)(Hm + kc * BK);
        #pragma unroll
        for (int i = 0; i < 4; ++i) {
            int idx = tid + i * 256;          // 0..1023
            int r = idx >> 3, c4 = idx & 7;
            *(uint4*)&sHn[r * LDT + c4 * 8] = srcn[r * 16 + c4];
            *(uint4*)&sHm[r * LDT + c4 * 8] = srcm[r * 16 + c4];
        }
        __syncthreads();

        #pragma unroll
        for (int kk = 0; kk < BK; kk += 16) {
            unsigned afr[4][4], bfr[4][2];
            #pragma unroll
            for (int i = 0; i < 4; ++i) {
                int r = wr + i * 16 + (lane >> 2);
                int c = kk + (lane & 3) * 2;
                afr[i][0] = *(const unsigned*)&sHn[r * LDT + c];
                afr[i][1] = *(const unsigned*)&sHn[(r + 8) * LDT + c];
                afr[i][2] = *(const unsigned*)&sHn[r * LDT + c + 8];
                afr[i][3] = *(const unsigned*)&sHn[(r + 8) * LDT + c + 8];
            }
            #pragma unroll
            for (int j = 0; j < 4; ++j) {
                int m = wc + j * 8 + (lane >> 2);
                int k = kk + (lane & 3) * 2;
                bfr[j][0] = *(const unsigned*)&sHm[m * LDT + k];
                bfr[j][1] = *(const unsigned*)&sHm[m * LDT + k + 8];
            }
            #pragma unroll
            for (int i = 0; i < 4; ++i)
                #pragma unroll
                for (int j = 0; j < 4; ++j)
                    mma16816(acc[i][j], afr[i], bfr[j]);
        }
    }

    // Fused epilogue: sd = relu(hsq_n + hsq_m - 2g); weight = adj[n,m] (+ adj[m,n] if offd)
    float esum = 0.f;
    const int r_l = wr + (lane >> 2);        // row within tile for this lane
    const int c_l = wc + (lane & 3) * 2;     // col within tile for this lane
    const float* adjA = adj + ((size_t)b * NN + bn0 + r_l) * NN + bm0 + c_l;
    const float* adjT = adj + ((size_t)b * NN + bm0 + c_l) * NN + bn0 + r_l;
    #pragma unroll
    for (int i = 0; i < 4; ++i) {
        #pragma unroll
        for (int j = 0; j < 4; ++j) {
            const float* pA = adjA + (size_t)(i * 16) * NN + j * 8;
            float2 a0 = *(const float2*)pA;
            float2 a1 = *(const float2*)(pA + (size_t)8 * NN);
            float w00 = a0.x, w01 = a0.y, w10 = a1.x, w11 = a1.y;
            if (offd) {
                // transposed tile: element (row = c, col = r) pairs with sd(r, c)
                const float* pT = adjT + (size_t)(j * 8) * NN + i * 16;
                w00 += pT[0];                        // (c,   r)
                w01 += pT[NN];                       // (c+1, r)
                w10 += pT[8];                        // (c,   r+8)
                w11 += pT[NN + 8];                   // (c+1, r+8)
            }
            int rl = wr + i * 16 + (lane >> 2);
            int cl = wc + j * 8 + (lane & 3) * 2;
            float hn0 = s_hsqn[rl], hn1 = s_hsqn[rl + 8];
            float hm0 = s_hsqm[cl], hm1 = s_hsqm[cl + 1];
            esum += w00 * fmaxf(hn0 + hm0 - 2.f * acc[i][j][0], 0.f);
            esum += w01 * fmaxf(hn0 + hm1 - 2.f * acc[i][j][1], 0.f);
            esum += w10 * fmaxf(hn1 + hm0 - 2.f * acc[i][j][2], 0.f);
            esum += w11 * fmaxf(hn1 + hm1 - 2.f * acc[i][j][3], 0.f);
        }
    }
    #pragma unroll
    for (int o = 16; o > 0; o >>= 1) esum += __shfl_down_sync(0xffffffffu, esum, o);
    if (lane == 0) s_red[w] = esum;
    __syncthreads();
    if (tid == 0) {
        float t = 0.f;
        #pragma unroll
        for (int i = 0; i < 8; ++i) t += s_red[i];
        g_partials[blockIdx.y * NPAIR + blockIdx.x] = t;
    }
}

// ---------------------------------------------------------------------------
// Deterministic final reduce in double
// ---------------------------------------------------------------------------
__global__ void reduce_kernel(float* __restrict__ out) {
    int tid = threadIdx.x;
    double s = 0.0;
    for (int i = tid; i < BATCH * NPAIR; i += 256) s += (double)g_partials[i];
    #pragma unroll
    for (int o = 16; o > 0; o >>= 1) s += __shfl_down_sync(0xffffffffu, s, o);
    __shared__ double sm[8];
    if ((tid & 31) == 0) sm[tid >> 5] = s;
    __syncthreads();
    if (tid == 0) {
        double t = 0.0;
        #pragma unroll
        for (int i = 0; i < 8; ++i) t += sm[i];
        out[0] = (float)(t / (double)(BATCH * NN));
    }
}

// ---------------------------------------------------------------------------
extern "C" void kernel_launch(void* const* d_in, const int* in_sizes, int n_in,
                              void* d_out, int out_size) {
    const float* adj = (const float*)d_in[0];
    const float* emb = (const float*)d_in[1];
    if (n_in >= 2 && in_sizes[0] < in_sizes[1]) {
        adj = (const float*)d_in[1];
        emb = (const float*)d_in[0];
    }

    prep_kernel<<<BATCH * NN / 16, 256>>>(emb);
    dim3 grid(NPAIR, BATCH);
    main_kernel<<<grid, 256>>>(adj);
    reduce_kernel<<<1, 256>>>((float*)d_out);
}